// round 11
// baseline (speedup 1.0000x reference)
#include <cuda_runtime.h>
#include <stdint.h>
#include <math.h>

// Fixed shapes
#define CDIM   64
#define HW     4096                 // 64*64
#define KCODES 512
#define NPTS   131072               // 32*4096
#define NQ     (NPTS*CDIM)          // 8388608
// Output layout: [loss(1) | quantized(NQ) | perplexity(1) | indices(NPTS)]
#define QOFF   1
#define POFF   (1+NQ)
#define IOFF   (2+NQ)

#define TPB      256                // 8 warps
#define PTS_WARP 16
#define PTS_CTA  128
#define NCTA     (NPTS/PTS_CTA)     // 1024
#define NCT      (KCODES/8)         // 64 code tiles of 8

// B in fragment order, PLAIN fp32 (split to tf32 on the fly in main).
// [ct][m(0..3)][lane] float4; +3 tiles of padding for prefetch overrun.
__device__ float g_B[(NCT+3)*4*32*4];
__device__ float g_se2[KCODES];
__device__ int   g_counts[KCODES];
__device__ float g_loss;
__device__ int   g_done;

__device__ __forceinline__ unsigned f2tf32(float v) {
    unsigned r;
    asm("cvt.rna.tf32.f32 %0, %1;" : "=r"(r) : "f"(v));
    return r;
}

#define MMA_TF32(d0,d1,d2,d3, a0,a1,a2,a3, b0,b1)                              \
    asm("mma.sync.aligned.m16n8k8.row.col.f32.tf32.tf32.f32 "                  \
        "{%0,%1,%2,%3}, {%4,%5,%6,%7}, {%8,%9}, {%0,%1,%2,%3};"                \
        : "+f"(d0), "+f"(d1), "+f"(d2), "+f"(d3)                               \
        : "r"(a0), "r"(a1), "r"(a2), "r"(a3), "r"(b0), "r"(b1))

// ---------------- prep: pack B (plain fp32, fragment order), se2, zeros ------
__global__ void __launch_bounds__(256)
vq_prep(const float* __restrict__ emb) {
    int id = blockIdx.x * 256 + threadIdx.x;
    if (id < NCT*4*32) {
        int ct   = id >> 7;
        int rest = id & 127;
        int m    = rest >> 5;
        int lane = rest & 31;
        float4 v4;
        float* vp = (float*)&v4;
        #pragma unroll
        for (int comp = 0; comp < 4; comp++) {
            int jh = m*4 + comp;
            int ks = jh >> 1, rg = jh & 1;
            int chan = ks*8 + (lane & 3) + rg*4;
            int code = ct*8 + (lane >> 2);
            vp[comp] = emb[chan*KCODES + code];
        }
        ((float4*)g_B)[(ct*4 + m)*32 + lane] = v4;
    } else if (id < NCT*4*32 + KCODES) {
        int k = id - NCT*4*32;
        float s = 0.0f;
        #pragma unroll 8
        for (int c = 0; c < CDIM; c++) {
            float v = emb[c*KCODES + k];
            s = fmaf(v, v, s);
        }
        g_se2[k] = s;
        g_counts[k] = 0;
        if (k == 0) { g_loss = 0.0f; g_done = 0; }
    }
}

// ---------------- main: distances + argmin (no quantized write) --------------

#define PREFETCH(CT, BF)                                                       \
    { _Pragma("unroll")                                                        \
      for (int m = 0; m < 4; m++) BF[m] = Bp[((CT)*4 + m)*32 + lane]; }

#define TILE_BODY(CT, BF)                                                      \
    {                                                                          \
        float hh0=0.f,hh1=0.f,hh2=0.f,hh3=0.f;                                 \
        float hl0=0.f,hl1=0.f,hl2=0.f,hl3=0.f;                                 \
        float lh0=0.f,lh1=0.f,lh2=0.f,lh3=0.f;                                 \
        _Pragma("unroll")                                                      \
        for (int ks = 0; ks < 8; ks++) {                                       \
            float v0, v1;                                                      \
            if ((ks & 1) == 0) { v0 = BF[ks>>1].x; v1 = BF[ks>>1].y; }         \
            else               { v0 = BF[ks>>1].z; v1 = BF[ks>>1].w; }         \
            unsigned bh0 = f2tf32(v0), bh1 = f2tf32(v1);                       \
            unsigned bl0 = f2tf32(v0 - __uint_as_float(bh0));                  \
            unsigned bl1 = f2tf32(v1 - __uint_as_float(bh1));                  \
            MMA_TF32(hh0,hh1,hh2,hh3,                                          \
                     ahi[ks*4+0],ahi[ks*4+1],ahi[ks*4+2],ahi[ks*4+3], bh0,bh1);\
            MMA_TF32(hl0,hl1,hl2,hl3,                                          \
                     ahi[ks*4+0],ahi[ks*4+1],ahi[ks*4+2],ahi[ks*4+3], bl0,bl1);\
            MMA_TF32(lh0,lh1,lh2,lh3,                                          \
                     alo[ks*4+0],alo[ks*4+1],alo[ks*4+2],alo[ks*4+3], bh0,bh1);\
        }                                                                      \
        float d0 = (hh0 + hl0) + lh0;                                          \
        float d1 = (hh1 + hl1) + lh1;                                          \
        float d2 = (hh2 + hl2) + lh2;                                          \
        float d3 = (hh3 + hl3) + lh3;                                          \
        int col = (CT)*8 + 2*t;                                                \
        float s0 = sse2[col], s1 = sse2[col+1];                                \
        float q0 = fmaf(-2.0f, d0, s0);                                        \
        float q1 = fmaf(-2.0f, d1, s1);                                        \
        float q2 = fmaf(-2.0f, d2, s0);                                        \
        float q3 = fmaf(-2.0f, d3, s1);                                        \
        if (q0 < best0 || (q0 == best0 && col   < bi0)) { best0 = q0; bi0 = col;   } \
        if (q1 < best0 || (q1 == best0 && col+1 < bi0)) { best0 = q1; bi0 = col+1; } \
        if (q2 < best1 || (q2 == best1 && col   < bi1)) { best1 = q2; bi1 = col;   } \
        if (q3 < best1 || (q3 == best1 && col+1 < bi1)) { best1 = q3; bi1 = col+1; } \
    }

__global__ void __launch_bounds__(TPB)
vq_main(const float* __restrict__ x, float* __restrict__ out) {
    __shared__ float sse2[KCODES];
    __shared__ int   shist[KCODES];
    __shared__ float wred[8];

    const int tid  = threadIdx.x;
    const int warp = tid >> 5;
    const int lane = tid & 31;
    const int g    = lane >> 2;     // group (row within tile)
    const int t    = lane & 3;      // thread-in-group

    sse2[tid]       = g_se2[tid];
    sse2[tid + TPB] = g_se2[tid + TPB];
    shist[tid] = 0; shist[tid + TPB] = 0;

    // ---- load this warp's 16 points as tf32-split A fragments --------------
    const int p0w = blockIdx.x * PTS_CTA + warp * PTS_WARP;
    const int b   = p0w >> 12;
    const int hw  = p0w & (HW - 1);
    const float* Base = x + (size_t)b * CDIM * HW + hw;

    unsigned ahi[32], alo[32];
    float zsq0 = 0.0f, zsq1 = 0.0f;
    #pragma unroll
    for (int ks = 0; ks < 8; ks++) {
        int c0 = ks*8 + t;
        float v0 = Base[g     + (size_t)c0      * HW];
        float v1 = Base[g + 8 + (size_t)c0      * HW];
        float v2 = Base[g     + (size_t)(c0+4)  * HW];
        float v3 = Base[g + 8 + (size_t)(c0+4)  * HW];
        zsq0 = fmaf(v0, v0, zsq0); zsq0 = fmaf(v2, v2, zsq0);
        zsq1 = fmaf(v1, v1, zsq1); zsq1 = fmaf(v3, v3, zsq1);
        unsigned h0 = f2tf32(v0), h1 = f2tf32(v1), h2 = f2tf32(v2), h3 = f2tf32(v3);
        ahi[ks*4+0] = h0; ahi[ks*4+1] = h1; ahi[ks*4+2] = h2; ahi[ks*4+3] = h3;
        alo[ks*4+0] = f2tf32(v0 - __uint_as_float(h0));
        alo[ks*4+1] = f2tf32(v1 - __uint_as_float(h1));
        alo[ks*4+2] = f2tf32(v2 - __uint_as_float(h2));
        alo[ks*4+3] = f2tf32(v3 - __uint_as_float(h3));
    }
    __syncthreads();

    // ---- 64 code tiles; coalesced loads, prefetch distance 3 ---------------
    float best0 = 3.4e38f, best1 = 3.4e38f;
    int   bi0 = 0, bi1 = 0;
    const float4* Bp = (const float4*)g_B;

    float4 B0[4], B1[4], B2[4], B3[4];
    PREFETCH(0, B0);
    PREFETCH(1, B1);
    PREFETCH(2, B2);
    #pragma unroll 1
    for (int ct = 0; ct < NCT; ct += 4) {
        PREFETCH(ct+3, B3); TILE_BODY(ct,   B0);
        PREFETCH(ct+4, B0); TILE_BODY(ct+1, B1);
        PREFETCH(ct+5, B1); TILE_BODY(ct+2, B2);
        PREFETCH(ct+6, B2); TILE_BODY(ct+3, B3);   // ct=60 -> prefetch 66 = pad
    }

    // ---- reduce across the 4 threads of each group (full butterfly) --------
    #pragma unroll
    for (int off = 1; off <= 2; off <<= 1) {
        float ob0 = __shfl_xor_sync(0xffffffffu, best0, off);
        int   oi0 = __shfl_xor_sync(0xffffffffu, bi0,   off);
        float ob1 = __shfl_xor_sync(0xffffffffu, best1, off);
        int   oi1 = __shfl_xor_sync(0xffffffffu, bi1,   off);
        float oz0 = __shfl_xor_sync(0xffffffffu, zsq0,  off);
        float oz1 = __shfl_xor_sync(0xffffffffu, zsq1,  off);
        if (ob0 < best0 || (ob0 == best0 && oi0 < bi0)) { best0 = ob0; bi0 = oi0; }
        if (ob1 < best1 || (ob1 == best1 && oi1 < bi1)) { best1 = ob1; bi1 = oi1; }
        zsq0 += oz0; zsq1 += oz1;
    }

    // ---- emit indices, hist, loss partial ----------------------------------
    float lsum = 0.0f;
    if (t == 0) {
        out[IOFF + p0w + g]     = (float)bi0;
        out[IOFF + p0w + g + 8] = (float)bi1;
        atomicAdd(&shist[bi0], 1);
        atomicAdd(&shist[bi1], 1);
        lsum = (best0 + zsq0) + (best1 + zsq1);   // true min squared distances
    }
    #pragma unroll
    for (int o = 16; o > 0; o >>= 1)
        lsum += __shfl_down_sync(0xffffffffu, lsum, o);
    if (lane == 0) wred[warp] = lsum;

    __syncthreads();
    // flush hist + loss
    { int h = shist[tid];       if (h) atomicAdd(&g_counts[tid], h);
      h     = shist[tid + TPB]; if (h) atomicAdd(&g_counts[tid + TPB], h); }
    if (tid < 8) {
        float v = wred[tid];
        #pragma unroll
        for (int o = 4; o > 0; o >>= 1)
            v += __shfl_down_sync(0xffu, v, o);
        if (tid == 0) atomicAdd(&g_loss, v);
    }
}

// ---------------- gather (+ fused finalize in last CTA) ----------------------
#define GCTA 128
#define GPTS (NPTS/GCTA)   // 1024 points per CTA
__global__ void __launch_bounds__(256)
vq_gather(const float* __restrict__ emb, float* __restrict__ out) {
    extern __shared__ float sE[];   // [64][512]
    const int tid  = threadIdx.x;
    const int warp = tid >> 5;
    const int lane = tid & 31;
    {
        const float4* e4 = (const float4*)emb;
        float4* s4 = (float4*)sE;
        #pragma unroll
        for (int i = tid; i < CDIM*KCODES/4; i += 256) s4[i] = e4[i];
    }
    __syncthreads();
    const int P0 = blockIdx.x * GPTS;
    #pragma unroll 1
    for (int pp = tid; pp < GPTS; pp += 256) {
        const int p  = P0 + pp;
        const int b  = p >> 12;
        const int hw = p & (HW - 1);
        const int bi = (int)out[IOFF + p];
        float* oq = out + QOFF + (size_t)b * CDIM * HW + hw;
        #pragma unroll 8
        for (int c = 0; c < CDIM; c++)
            oq[(size_t)c * HW] = sE[c * KCODES + bi];
    }

    // ---- last CTA computes loss + perplexity -------------------------------
    __syncthreads();
    __threadfence();
    __shared__ int s_rank;
    if (tid == 0) s_rank = atomicAdd(&g_done, 1);
    __syncthreads();
    if (s_rank == GCTA - 1) {
        float v = 0.0f;
        #pragma unroll
        for (int k = tid; k < KCODES; k += 256) {
            float pr = (float)g_counts[k] * (1.0f / (float)NPTS);
            v += pr * logf(pr + 1e-10f);
        }
        #pragma unroll
        for (int o = 16; o > 0; o >>= 1)
            v += __shfl_down_sync(0xffffffffu, v, o);
        if (lane == 0) sE[warp] = v;
        __syncthreads();
        if (tid < 8) {
            float s = sE[tid];
            #pragma unroll
            for (int o = 4; o > 0; o >>= 1)
                s += __shfl_down_sync(0xffu, s, o);
            if (tid == 0) {
                // loss = q_latent + 0.25*e_latent; both equal mean((q-z)^2)
                out[0]    = g_loss * (1.25f / (float)NQ);
                out[POFF] = expf(-s);
            }
        }
    }
}

extern "C" void kernel_launch(void* const* d_in, const int* in_sizes, int n_in,
                              void* d_out, int out_size) {
    const float* x   = (const float*)d_in[0];
    const float* emb = (const float*)d_in[1];
    float* out = (float*)d_out;

    cudaFuncSetAttribute(vq_gather, cudaFuncAttributeMaxDynamicSharedMemorySize,
                         CDIM*KCODES*4);

    vq_prep<<<(NCT*4*32 + KCODES + 255)/256, 256>>>(emb);
    vq_main<<<NCTA, TPB>>>(x, out);
    vq_gather<<<GCTA, 256, CDIM*KCODES*4>>>(emb, out);
}

// round 12
// speedup vs baseline: 2.2104x; 2.2104x over previous
#include <cuda_runtime.h>
#include <cuda_fp16.h>
#include <stdint.h>
#include <math.h>

// Fixed shapes
#define CDIM   64
#define HW     4096                 // 64*64
#define KCODES 512
#define NPTS   131072               // 32*4096
#define NQ     (NPTS*CDIM)          // 8388608
// Output layout: [loss(1) | quantized(NQ) | perplexity(1) | indices(NPTS)]
#define QOFF   1
#define POFF   (1+NQ)
#define IOFF   (2+NQ)

#define TPB      256                // 8 warps
#define PTS_WARP 16
#define PTS_CTA  128
#define NCTA     (NPTS/PTS_CTA)     // 1024
#define NCT      (KCODES/8)         // 64 code tiles of 8

// B fp16 fragments, prep-split hi/lo, fragment order, coalesced:
// [ct][qq(0..3)][lane] uint4.  qq: 0=hi kb0-1, 1=hi kb2-3, 2=lo kb0-1, 3=lo kb2-3
// +3 tiles padding for prefetch overrun.
__device__ uint4 g_B[(NCT+3)*4*32];
__device__ float g_se2[KCODES];
__device__ int   g_counts[KCODES];
__device__ float g_loss;
__device__ int   g_done;

__device__ __forceinline__ unsigned packh2(float x, float y) {
    __half2 h = __floats2half2_rn(x, y);
    return *(unsigned*)&h;
}
// split v into fp16 hi + fp16 lo (v ~= hi + lo, residual ~2^-22 |v|)
__device__ __forceinline__ void split2(float x, float y,
                                       unsigned& hi, unsigned& lo) {
    __half hx = __float2half_rn(x), hy = __float2half_rn(y);
    float  rx = x - __half2float(hx), ry = y - __half2float(hy);
    __half2 h = __halves2half2(hx, hy);
    hi = *(unsigned*)&h;
    lo = packh2(rx, ry);
}

#define MMA_F16(d0,d1,d2,d3, a0,a1,a2,a3, b0,b1)                               \
    asm("mma.sync.aligned.m16n8k16.row.col.f32.f16.f16.f32 "                   \
        "{%0,%1,%2,%3}, {%4,%5,%6,%7}, {%8,%9}, {%0,%1,%2,%3};"                \
        : "+f"(d0), "+f"(d1), "+f"(d2), "+f"(d3)                               \
        : "r"(a0), "r"(a1), "r"(a2), "r"(a3), "r"(b0), "r"(b1))

// ---------------- prep: pack B fp16 hi/lo fragments, se2, zeros --------------
__global__ void __launch_bounds__(256)
vq_prep(const float* __restrict__ emb) {
    int id = blockIdx.x * 256 + threadIdx.x;
    if (id < NCT*4*32) {
        int ct   = id >> 7;
        int qq   = (id >> 5) & 3;
        int lane = id & 31;
        int g = lane >> 2, t = lane & 3;
        int split = qq >> 1, halfp = qq & 1;
        int code  = ct*8 + g;
        unsigned v[4];
        #pragma unroll
        for (int comp = 0; comp < 4; comp++) {
            int kb = halfp*2 + (comp >> 1);
            int r  = comp & 1;
            int c0 = kb*16 + 2*t + r*8;       // b-reg r: K rows 2t(+8), 2t+1(+8)
            float f0 = emb[c0*KCODES + code];
            float f1 = emb[(c0+1)*KCODES + code];
            unsigned hi, lo;
            split2(f0, f1, hi, lo);
            v[comp] = split ? lo : hi;
        }
        g_B[(ct*4 + qq)*32 + lane] = make_uint4(v[0], v[1], v[2], v[3]);
    } else if (id < NCT*4*32 + KCODES) {
        int k = id - NCT*4*32;
        float s = 0.0f;
        #pragma unroll 8
        for (int c = 0; c < CDIM; c++) {
            float v = emb[c*KCODES + k];
            s = fmaf(v, v, s);
        }
        g_se2[k] = s;
        g_counts[k] = 0;
        if (k == 0) { g_loss = 0.0f; g_done = 0; }
    }
}

// ---------------- main: distances + argmin -----------------------------------

#define PREFETCH(CT, BF)                                                       \
    { _Pragma("unroll")                                                        \
      for (int m = 0; m < 4; m++) BF[m] = Bp[((CT)*4 + m)*32 + lane]; }

#define TILE_BODY(CT, BF)                                                      \
    {                                                                          \
        float hh0=0.f,hh1=0.f,hh2=0.f,hh3=0.f;                                 \
        float hl0=0.f,hl1=0.f,hl2=0.f,hl3=0.f;                                 \
        float lh0=0.f,lh1=0.f,lh2=0.f,lh3=0.f;                                 \
        _Pragma("unroll")                                                      \
        for (int kb = 0; kb < 4; kb++) {                                       \
            uint4 H = BF[kb>>1];                                               \
            uint4 L = BF[2 + (kb>>1)];                                         \
            unsigned bh0, bh1, bl0, bl1;                                       \
            if ((kb & 1) == 0) { bh0=H.x; bh1=H.y; bl0=L.x; bl1=L.y; }         \
            else               { bh0=H.z; bh1=H.w; bl0=L.z; bl1=L.w; }         \
            MMA_F16(hh0,hh1,hh2,hh3,                                           \
                    ah[kb*4+0],ah[kb*4+1],ah[kb*4+2],ah[kb*4+3], bh0,bh1);     \
            MMA_F16(hl0,hl1,hl2,hl3,                                           \
                    ah[kb*4+0],ah[kb*4+1],ah[kb*4+2],ah[kb*4+3], bl0,bl1);     \
            MMA_F16(lh0,lh1,lh2,lh3,                                           \
                    al[kb*4+0],al[kb*4+1],al[kb*4+2],al[kb*4+3], bh0,bh1);     \
        }                                                                      \
        float d0 = (hh0 + hl0) + lh0;                                          \
        float d1 = (hh1 + hl1) + lh1;                                          \
        float d2 = (hh2 + hl2) + lh2;                                          \
        float d3 = (hh3 + hl3) + lh3;                                          \
        int col = (CT)*8 + 2*t;                                                \
        float s0 = sse2[col], s1 = sse2[col+1];                                \
        float q0 = fmaf(-2.0f, d0, s0);                                        \
        float q1 = fmaf(-2.0f, d1, s1);                                        \
        float q2 = fmaf(-2.0f, d2, s0);                                        \
        float q3 = fmaf(-2.0f, d3, s1);                                        \
        if (q0 < best0 || (q0 == best0 && col   < bi0)) { best0 = q0; bi0 = col;   } \
        if (q1 < best0 || (q1 == best0 && col+1 < bi0)) { best0 = q1; bi0 = col+1; } \
        if (q2 < best1 || (q2 == best1 && col   < bi1)) { best1 = q2; bi1 = col;   } \
        if (q3 < best1 || (q3 == best1 && col+1 < bi1)) { best1 = q3; bi1 = col+1; } \
    }

__global__ void __launch_bounds__(TPB)
vq_main(const float* __restrict__ x, float* __restrict__ out) {
    __shared__ float sse2[KCODES];
    __shared__ int   shist[KCODES];
    __shared__ float wred[8];

    const int tid  = threadIdx.x;
    const int warp = tid >> 5;
    const int lane = tid & 31;
    const int g    = lane >> 2;     // group (row within A tile / code within B)
    const int t    = lane & 3;      // thread-in-group

    sse2[tid]       = g_se2[tid];
    sse2[tid + TPB] = g_se2[tid + TPB];
    shist[tid] = 0; shist[tid + TPB] = 0;

    // ---- load this warp's 16 points as fp16-split A fragments --------------
    // m16n8k16 A layout: a0=(g, 2t|2t+1), a1=(g+8, ..), a2=(g, 2t+8|2t+9), a3=(g+8, ..)
    const int p0w = blockIdx.x * PTS_CTA + warp * PTS_WARP;
    const int b   = p0w >> 12;
    const int hw  = p0w & (HW - 1);
    const float* Base = x + (size_t)b * CDIM * HW + hw;

    unsigned ah[16], al[16];
    float zsq0 = 0.0f, zsq1 = 0.0f;
    #pragma unroll
    for (int kb = 0; kb < 4; kb++) {
        int cb = kb*16 + 2*t;
        float f00 = Base[g     + (size_t)(cb    ) * HW];
        float f01 = Base[g     + (size_t)(cb + 1) * HW];
        float f10 = Base[g + 8 + (size_t)(cb    ) * HW];
        float f11 = Base[g + 8 + (size_t)(cb + 1) * HW];
        float f20 = Base[g     + (size_t)(cb + 8) * HW];
        float f21 = Base[g     + (size_t)(cb + 9) * HW];
        float f30 = Base[g + 8 + (size_t)(cb + 8) * HW];
        float f31 = Base[g + 8 + (size_t)(cb + 9) * HW];
        zsq0 = fmaf(f00,f00, fmaf(f01,f01, fmaf(f20,f20, fmaf(f21,f21, zsq0))));
        zsq1 = fmaf(f10,f10, fmaf(f11,f11, fmaf(f30,f30, fmaf(f31,f31, zsq1))));
        split2(f00, f01, ah[kb*4+0], al[kb*4+0]);
        split2(f10, f11, ah[kb*4+1], al[kb*4+1]);
        split2(f20, f21, ah[kb*4+2], al[kb*4+2]);
        split2(f30, f31, ah[kb*4+3], al[kb*4+3]);
    }
    __syncthreads();

    // ---- 64 code tiles; coalesced loads, prefetch distance 3 ---------------
    float best0 = 3.4e38f, best1 = 3.4e38f;
    int   bi0 = 0, bi1 = 0;
    const uint4* Bp = g_B;

    uint4 B0[4], B1[4], B2[4], B3[4];
    PREFETCH(0, B0);
    PREFETCH(1, B1);
    PREFETCH(2, B2);
    #pragma unroll 1
    for (int ct = 0; ct < NCT; ct += 4) {
        PREFETCH(ct+3, B3); TILE_BODY(ct,   B0);
        PREFETCH(ct+4, B0); TILE_BODY(ct+1, B1);
        PREFETCH(ct+5, B1); TILE_BODY(ct+2, B2);
        PREFETCH(ct+6, B2); TILE_BODY(ct+3, B3);   // ct=60 -> prefetch 66 = pad
    }

    // ---- reduce across the 4 threads of each group (full butterfly) --------
    #pragma unroll
    for (int off = 1; off <= 2; off <<= 1) {
        float ob0 = __shfl_xor_sync(0xffffffffu, best0, off);
        int   oi0 = __shfl_xor_sync(0xffffffffu, bi0,   off);
        float ob1 = __shfl_xor_sync(0xffffffffu, best1, off);
        int   oi1 = __shfl_xor_sync(0xffffffffu, bi1,   off);
        float oz0 = __shfl_xor_sync(0xffffffffu, zsq0,  off);
        float oz1 = __shfl_xor_sync(0xffffffffu, zsq1,  off);
        if (ob0 < best0 || (ob0 == best0 && oi0 < bi0)) { best0 = ob0; bi0 = oi0; }
        if (ob1 < best1 || (ob1 == best1 && oi1 < bi1)) { best1 = ob1; bi1 = oi1; }
        zsq0 += oz0; zsq1 += oz1;
    }

    // ---- emit indices, hist, loss partial ----------------------------------
    float lsum = 0.0f;
    if (t == 0) {
        out[IOFF + p0w + g]     = (float)bi0;
        out[IOFF + p0w + g + 8] = (float)bi1;
        atomicAdd(&shist[bi0], 1);
        atomicAdd(&shist[bi1], 1);
        lsum = (best0 + zsq0) + (best1 + zsq1);   // true min squared distances
    }
    #pragma unroll
    for (int o = 16; o > 0; o >>= 1)
        lsum += __shfl_down_sync(0xffffffffu, lsum, o);
    if (lane == 0) wred[warp] = lsum;

    __syncthreads();
    // flush hist + loss
    { int h = shist[tid];       if (h) atomicAdd(&g_counts[tid], h);
      h     = shist[tid + TPB]; if (h) atomicAdd(&g_counts[tid + TPB], h); }
    if (tid < 8) {
        float v = wred[tid];
        #pragma unroll
        for (int o = 4; o > 0; o >>= 1)
            v += __shfl_down_sync(0xffu, v, o);
        if (tid == 0) atomicAdd(&g_loss, v);
    }
}

// ---------------- gather (+ fused finalize in last CTA) ----------------------
#define GCTA 128
#define GPTS (NPTS/GCTA)   // 1024 points per CTA
__global__ void __launch_bounds__(256)
vq_gather(const float* __restrict__ emb, float* __restrict__ out) {
    extern __shared__ float sE[];   // [64][512]
    const int tid  = threadIdx.x;
    const int warp = tid >> 5;
    const int lane = tid & 31;
    {
        const float4* e4 = (const float4*)emb;
        float4* s4 = (float4*)sE;
        #pragma unroll
        for (int i = tid; i < CDIM*KCODES/4; i += 256) s4[i] = e4[i];
    }
    __syncthreads();
    const int P0 = blockIdx.x * GPTS;
    #pragma unroll 1
    for (int pp = tid; pp < GPTS; pp += 256) {
        const int p  = P0 + pp;
        const int b  = p >> 12;
        const int hw = p & (HW - 1);
        const int bi = (int)out[IOFF + p];
        float* oq = out + QOFF + (size_t)b * CDIM * HW + hw;
        #pragma unroll 8
        for (int c = 0; c < CDIM; c++)
            oq[(size_t)c * HW] = sE[c * KCODES + bi];
    }

    // ---- last CTA computes loss + perplexity -------------------------------
    __syncthreads();
    __threadfence();
    __shared__ int s_rank;
    if (tid == 0) s_rank = atomicAdd(&g_done, 1);
    __syncthreads();
    if (s_rank == GCTA - 1) {
        float v = 0.0f;
        #pragma unroll
        for (int k = tid; k < KCODES; k += 256) {
            float pr = (float)g_counts[k] * (1.0f / (float)NPTS);
            v += pr * logf(pr + 1e-10f);
        }
        #pragma unroll
        for (int o = 16; o > 0; o >>= 1)
            v += __shfl_down_sync(0xffffffffu, v, o);
        if (lane == 0) sE[warp] = v;
        __syncthreads();
        if (tid < 8) {
            float s = sE[tid];
            #pragma unroll
            for (int o = 4; o > 0; o >>= 1)
                s += __shfl_down_sync(0xffu, s, o);
            if (tid == 0) {
                // loss = q_latent + 0.25*e_latent; both equal mean((q-z)^2)
                out[0]    = g_loss * (1.25f / (float)NQ);
                out[POFF] = expf(-s);
            }
        }
    }
}

extern "C" void kernel_launch(void* const* d_in, const int* in_sizes, int n_in,
                              void* d_out, int out_size) {
    const float* x   = (const float*)d_in[0];
    const float* emb = (const float*)d_in[1];
    float* out = (float*)d_out;

    cudaFuncSetAttribute(vq_gather, cudaFuncAttributeMaxDynamicSharedMemorySize,
                         CDIM*KCODES*4);

    vq_prep<<<(NCT*4*32 + KCODES + 255)/256, 256>>>(emb);
    vq_main<<<NCTA, TPB>>>(x, out);
    vq_gather<<<GCTA, 256, CDIM*KCODES*4>>>(emb, out);
}